// round 9
// baseline (speedup 1.0000x reference)
#include <cuda_runtime.h>
#include <cuda_bf16.h>
#include <cstdint>

constexpr int NN   = 50000;
constexpr int EMAX = 640000;

__device__ int   g_cnt[NN];
__device__ int   g_fill[NN];
__device__ int   g_rowptr[NN + 1];
__device__ int   g_col[EMAX];
__device__ float g_agg1[(size_t)NN * 128];   // mean of x (f32)
__device__ float g_h[(size_t)NN * 256];      // layer-1 output (f32)
__device__ float g_c2[(size_t)NN * 256];     // [y | part] (f32)

// ---------------------------------------------------------------------------
// CSR build
// ---------------------------------------------------------------------------
__global__ void zero_cnt() {
    int i = blockIdx.x * blockDim.x + threadIdx.x;
    if (i < NN) g_cnt[i] = 0;
}

__global__ void hist_kernel(const int* __restrict__ dst, int E) {
    int i = blockIdx.x * blockDim.x + threadIdx.x;
    int stride = gridDim.x * blockDim.x;
    for (; i < E; i += stride)
        atomicAdd(&g_cnt[dst[i]], 1);
}

__global__ void __launch_bounds__(1024, 1) scan_kernel() {
    __shared__ int sums[1024];
    const int tid = threadIdx.x;
    const int CH = (NN + 1023) / 1024;
    const int base = tid * CH;

    int local = 0;
    for (int i = 0; i < CH; i++) {
        int idx = base + i;
        if (idx < NN) local += g_cnt[idx];
    }
    sums[tid] = local;
    __syncthreads();
    for (int d = 1; d < 1024; d <<= 1) {
        int v = (tid >= d) ? sums[tid - d] : 0;
        __syncthreads();
        sums[tid] += v;
        __syncthreads();
    }
    int off = sums[tid] - local;
    for (int i = 0; i < CH; i++) {
        int idx = base + i;
        if (idx < NN) {
            g_rowptr[idx] = off;
            g_fill[idx] = off;
            off += g_cnt[idx];
        }
    }
    if (tid == 1023) g_rowptr[NN] = off;
}

__global__ void place_kernel(const int* __restrict__ src,
                             const int* __restrict__ dst, int E) {
    int i = blockIdx.x * blockDim.x + threadIdx.x;
    int stride = gridDim.x * blockDim.x;
    for (; i < E; i += stride) {
        int pos = atomicAdd(&g_fill[dst[i]], 1);
        g_col[pos] = src[i];
    }
}

// ---------------------------------------------------------------------------
// Gather-mean: one warp per node, 1 float4 per lane, 4-deep unroll.
// ---------------------------------------------------------------------------
template <int FIN>
__global__ void __launch_bounds__(256)
gather_mean(const float* __restrict__ feat, int fstride,
            const float* __restrict__ c2,
            const float* __restrict__ b2,
            float* __restrict__ out) {
    int node = (blockIdx.x * blockDim.x + threadIdx.x) >> 5;
    if (node >= NN) return;
    int lane = threadIdx.x & 31;
    int beg = __ldg(&g_rowptr[node]);
    int end = __ldg(&g_rowptr[node + 1]);

    float4 a0 = make_float4(0.f, 0.f, 0.f, 0.f);
    float4 a1 = make_float4(0.f, 0.f, 0.f, 0.f);
    float4 a2 = make_float4(0.f, 0.f, 0.f, 0.f);
    float4 a3 = make_float4(0.f, 0.f, 0.f, 0.f);
    int e = beg;
    for (; e + 3 < end; e += 4) {
        int s0 = __ldg(&g_col[e]);
        int s1 = __ldg(&g_col[e + 1]);
        int s2 = __ldg(&g_col[e + 2]);
        int s3 = __ldg(&g_col[e + 3]);
        float4 v0 = __ldg(reinterpret_cast<const float4*>(feat + (size_t)s0 * fstride) + lane);
        float4 v1 = __ldg(reinterpret_cast<const float4*>(feat + (size_t)s1 * fstride) + lane);
        float4 v2 = __ldg(reinterpret_cast<const float4*>(feat + (size_t)s2 * fstride) + lane);
        float4 v3 = __ldg(reinterpret_cast<const float4*>(feat + (size_t)s3 * fstride) + lane);
        a0.x += v0.x; a0.y += v0.y; a0.z += v0.z; a0.w += v0.w;
        a1.x += v1.x; a1.y += v1.y; a1.z += v1.z; a1.w += v1.w;
        a2.x += v2.x; a2.y += v2.y; a2.z += v2.z; a2.w += v2.w;
        a3.x += v3.x; a3.y += v3.y; a3.z += v3.z; a3.w += v3.w;
    }
    for (; e < end; e++) {
        int s0 = __ldg(&g_col[e]);
        float4 v0 = __ldg(reinterpret_cast<const float4*>(feat + (size_t)s0 * fstride) + lane);
        a0.x += v0.x; a0.y += v0.y; a0.z += v0.z; a0.w += v0.w;
    }
    float inv = 1.0f / (float)max(end - beg, 1);
    float4 r;
    r.x = (a0.x + a1.x + a2.x + a3.x) * inv;
    r.y = (a0.y + a1.y + a2.y + a3.y) * inv;
    r.z = (a0.z + a1.z + a2.z + a3.z) * inv;
    r.w = (a0.w + a1.w + a2.w + a3.w) * inv;

    if (FIN) {
        float4 p = *reinterpret_cast<const float4*>(c2 + (size_t)node * 256 + 128 + lane * 4);
        float4 b = __ldg(reinterpret_cast<const float4*>(b2) + lane);
        r.x += p.x + b.x;
        r.y += p.y + b.y;
        r.z += p.z + b.z;
        r.w += p.w + b.w;
    }
    *(reinterpret_cast<float4*>(out + (size_t)node * 128) + lane) = r;
}

// ---------------------------------------------------------------------------
// mma.sync m16n8k16 bf16 + split helpers
// ---------------------------------------------------------------------------
__device__ __forceinline__ void mma_bf16(float* d, const uint32_t* a,
                                         const uint32_t* b) {
    asm volatile(
        "mma.sync.aligned.m16n8k16.row.col.f32.bf16.bf16.f32 "
        "{%0,%1,%2,%3}, {%4,%5,%6,%7}, {%8,%9}, {%0,%1,%2,%3};"
        : "+f"(d[0]), "+f"(d[1]), "+f"(d[2]), "+f"(d[3])
        : "r"(a[0]), "r"(a[1]), "r"(a[2]), "r"(a[3]), "r"(b[0]), "r"(b[1]));
}

__device__ __forceinline__ void split2(float x, float y,
                                       uint32_t& hi, uint32_t& lo) {
    __nv_bfloat162 h = __floats2bfloat162_rn(x, y);
    __nv_bfloat162 l = __floats2bfloat162_rn(x - __bfloat162float(h.x),
                                             y - __bfloat162float(h.y));
    hi = *reinterpret_cast<uint32_t*>(&h);
    lo = *reinterpret_cast<uint32_t*>(&l);
}

__device__ __forceinline__ void cp_async16(uint32_t saddr, const void* gaddr,
                                           uint32_t src_bytes) {
    asm volatile("cp.async.cg.shared.global [%0], [%1], 16, %2;"
                 :: "r"(saddr), "l"(gaddr), "r"(src_bytes));
}

// ---------------------------------------------------------------------------
// Split-bf16 HMMA GEMM (R5 structure) + cp.async double-buffered f32 staging.
// C[M,256] = act(A[M,256] @ B[256,256]^T (+bias)); 3-term split, fp32 accum.
// SMEM: [stageA0|stageB0|stageA1|stageB1] f32 (64KB) + bf16 planes (40KB).
// Per chunk: issue cp.async for ch+1 -> wait ch -> sync -> convert (smem f32
// -> bf16 planes; zero extra registers) -> sync -> MMA.
// MODE 1: A = [agg1 | x], relu+bias.   MODE 2: A = h.
// ---------------------------------------------------------------------------
constexpr int PAD = 40;
constexpr int PLANE = 128 * PAD;                      // bf16 elems per plane
constexpr int STAGE_F = 128 * 32;                     // f32 per staged matrix
constexpr int GEMM_DSMEM = 4 * STAGE_F * 4 + 4 * PLANE * 2;   // 65536 + 40960

template <int MODE>
__global__ void __launch_bounds__(256, 2)
sage_gemm(const float* __restrict__ A0, const float* __restrict__ A1,
          const float* __restrict__ B0, const float* __restrict__ B1,
          const float* __restrict__ bias,
          float* __restrict__ C, int M) {
    extern __shared__ char dynsmem[];
    float* stage = reinterpret_cast<float*>(dynsmem);           // 4*STAGE_F f32
    __nv_bfloat16* planes = reinterpret_cast<__nv_bfloat16*>(dynsmem + 4 * STAGE_F * 4);
    __nv_bfloat16* AH = planes;
    __nv_bfloat16* AL = AH + PLANE;
    __nv_bfloat16* BH = AL + PLANE;
    __nv_bfloat16* BL = BH + PLANE;

    const int tid = threadIdx.x;
    const int wid = tid >> 5, lane = tid & 31;
    const int wm = wid & 3, wn = wid >> 2;
    const int m0 = blockIdx.x * 128, n0 = blockIdx.y * 128;

    float acc[2][8][4];
#pragma unroll
    for (int i = 0; i < 2; i++)
#pragma unroll
        for (int j = 0; j < 8; j++)
#pragma unroll
            for (int q = 0; q < 4; q++) acc[i][j][q] = 0.f;

    const uint32_t stage_base = (uint32_t)__cvta_generic_to_shared(stage);

    // issue cp.async for chunk ch into staging buffer s (4 A + 4 B per thread)
    auto issue = [&](int ch, int s) {
        uint32_t sa = stage_base + (uint32_t)(2 * s) * (STAGE_F * 4);
        uint32_t sb = sa + STAGE_F * 4;
#pragma unroll
        for (int it = 0; it < 4; it++) {
            int idx = it * 256 + tid;
            int row = idx >> 3, f = idx & 7;
            // ---- A ----
            int gm = m0 + row;
            const float* ap;
            uint32_t abytes = (gm < M) ? 16u : 0u;
            int gmc = (gm < M) ? gm : 0;
            if (MODE == 1) {
                ap = ((ch < 4) ? A0 : A1) + (size_t)gmc * 128
                     + ((ch < 4) ? ch : ch - 4) * 32 + f * 4;
            } else {
                ap = A0 + (size_t)gmc * 256 + ch * 32 + f * 4;
            }
            cp_async16(sa + (uint32_t)idx * 16, ap, abytes);
            // ---- B ----
            const float* bp;
            if (MODE == 1) {
                bp = ((ch < 4) ? B0 : B1) + (size_t)(n0 + row) * 128
                     + ((ch < 4) ? ch : ch - 4) * 32 + f * 4;
            } else {
                const float* base = (n0 == 0) ? B0 : B1;
                bp = base + (size_t)row * 256 + ch * 32 + f * 4;
            }
            cp_async16(sb + (uint32_t)idx * 16, bp, 16u);
        }
        asm volatile("cp.async.commit_group;");
    };

    issue(0, 0);

    for (int ch = 0; ch < 8; ch++) {
        const int s = ch & 1;
        if (ch < 7) {
            issue(ch + 1, s ^ 1);
            asm volatile("cp.async.wait_group 1;");
        } else {
            asm volatile("cp.async.wait_group 0;");
        }
        __syncthreads();   // stage[s] visible to all; prior MMA reads done

        // ---- convert staged f32 -> bf16 planes (conflict-free: addr = 4*idx) ----
        const float* stA = stage + (size_t)(2 * s) * STAGE_F;
        const float* stB = stA + STAGE_F;
#pragma unroll
        for (int it = 0; it < 4; it++) {
            int idx = it * 256 + tid;
            int row = idx >> 3, f = idx & 7;
            int off = row * PAD + f * 4;
            float4 v = *reinterpret_cast<const float4*>(stA + (size_t)idx * 4);
            uint32_t h01, l01, h23, l23;
            split2(v.x, v.y, h01, l01);
            split2(v.z, v.w, h23, l23);
            *reinterpret_cast<uint2*>(&AH[off]) = make_uint2(h01, h23);
            *reinterpret_cast<uint2*>(&AL[off]) = make_uint2(l01, l23);
            v = *reinterpret_cast<const float4*>(stB + (size_t)idx * 4);
            split2(v.x, v.y, h01, l01);
            split2(v.z, v.w, h23, l23);
            *reinterpret_cast<uint2*>(&BH[off]) = make_uint2(h01, h23);
            *reinterpret_cast<uint2*>(&BL[off]) = make_uint2(l01, l23);
        }
        __syncthreads();   // planes ready

        // ---- MMA (identical to R5) ----
        const int r = lane >> 2, c = (lane & 3) * 2;
#pragma unroll
        for (int ks = 0; ks < 2; ks++) {
            const int k = ks * 16;
            uint32_t ahi[2][4], alo[2][4];
#pragma unroll
            for (int mt = 0; mt < 2; mt++) {
                int rr = wm * 32 + mt * 16 + r;
                ahi[mt][0] = *reinterpret_cast<const uint32_t*>(&AH[rr * PAD + k + c]);
                ahi[mt][1] = *reinterpret_cast<const uint32_t*>(&AH[(rr + 8) * PAD + k + c]);
                ahi[mt][2] = *reinterpret_cast<const uint32_t*>(&AH[rr * PAD + k + c + 8]);
                ahi[mt][3] = *reinterpret_cast<const uint32_t*>(&AH[(rr + 8) * PAD + k + c + 8]);
                alo[mt][0] = *reinterpret_cast<const uint32_t*>(&AL[rr * PAD + k + c]);
                alo[mt][1] = *reinterpret_cast<const uint32_t*>(&AL[(rr + 8) * PAD + k + c]);
                alo[mt][2] = *reinterpret_cast<const uint32_t*>(&AL[rr * PAD + k + c + 8]);
                alo[mt][3] = *reinterpret_cast<const uint32_t*>(&AL[(rr + 8) * PAD + k + c + 8]);
            }
#pragma unroll
            for (int nt = 0; nt < 8; nt++) {
                int nn = wn * 64 + nt * 8 + (lane >> 2);
                int kb = k + (lane & 3) * 2;
                uint32_t bhi[2], blo[2];
                bhi[0] = *reinterpret_cast<const uint32_t*>(&BH[nn * PAD + kb]);
                bhi[1] = *reinterpret_cast<const uint32_t*>(&BH[nn * PAD + kb + 8]);
                blo[0] = *reinterpret_cast<const uint32_t*>(&BL[nn * PAD + kb]);
                blo[1] = *reinterpret_cast<const uint32_t*>(&BL[nn * PAD + kb + 8]);
#pragma unroll
                for (int mt = 0; mt < 2; mt++) {
                    mma_bf16(acc[mt][nt], ahi[mt], bhi);
                    mma_bf16(acc[mt][nt], ahi[mt], blo);
                    mma_bf16(acc[mt][nt], alo[mt], bhi);
                }
            }
        }
        __syncthreads();   // MMA reads done before next convert overwrites planes
    }

    // ---- epilogue (f32 out) ----
#pragma unroll
    for (int mt = 0; mt < 2; mt++) {
#pragma unroll
        for (int nt = 0; nt < 8; nt++) {
            int m = m0 + wm * 32 + mt * 16 + (lane >> 2);
            int n = n0 + wn * 64 + nt * 8 + (lane & 3) * 2;
            float2 bz = make_float2(0.f, 0.f);
            if (MODE == 1)
                bz = *reinterpret_cast<const float2*>(bias + n);
            if (m < M) {
                float2 v;
                v.x = acc[mt][nt][0] + bz.x;
                v.y = acc[mt][nt][1] + bz.y;
                if (MODE == 1) { v.x = fmaxf(v.x, 0.f); v.y = fmaxf(v.y, 0.f); }
                *reinterpret_cast<float2*>(C + (size_t)m * 256 + n) = v;
            }
            if (m + 8 < M) {
                float2 v;
                v.x = acc[mt][nt][2] + bz.x;
                v.y = acc[mt][nt][3] + bz.y;
                if (MODE == 1) { v.x = fmaxf(v.x, 0.f); v.y = fmaxf(v.y, 0.f); }
                *reinterpret_cast<float2*>(C + (size_t)(m + 8) * 256 + n) = v;
            }
        }
    }
}

// ---------------------------------------------------------------------------
// Launch
// ---------------------------------------------------------------------------
extern "C" void kernel_launch(void* const* d_in, const int* in_sizes, int n_in,
                              void* d_out, int out_size) {
    const float* x    = (const float*)d_in[0];
    const int*   ei   = (const int*)d_in[1];
    const float* W1_l = (const float*)d_in[2];
    const float* b1_l = (const float*)d_in[3];
    const float* W1_r = (const float*)d_in[4];
    const float* W2_l = (const float*)d_in[5];
    const float* b2_l = (const float*)d_in[6];
    const float* W2_r = (const float*)d_in[7];
    float* out = (float*)d_out;

    const int E = in_sizes[1] / 2;
    const int* esrc = ei;
    const int* edst = ei + E;

    void *p_agg1, *p_h, *p_c2;
    cudaGetSymbolAddress(&p_agg1, g_agg1);
    cudaGetSymbolAddress(&p_h,    g_h);
    cudaGetSymbolAddress(&p_c2,   g_c2);
    float* agg1 = (float*)p_agg1;
    float* hbuf = (float*)p_h;
    float* c2   = (float*)p_c2;

    cudaFuncSetAttribute(sage_gemm<1>,
                         cudaFuncAttributeMaxDynamicSharedMemorySize, GEMM_DSMEM);
    cudaFuncSetAttribute(sage_gemm<2>,
                         cudaFuncAttributeMaxDynamicSharedMemorySize, GEMM_DSMEM);

    // ---- CSR build (by dst) ----
    zero_cnt<<<(NN + 255) / 256, 256>>>();
    hist_kernel<<<(E + 511) / 512, 256>>>(edst, E);
    scan_kernel<<<1, 1024>>>();
    place_kernel<<<(E + 511) / 512, 256>>>(esrc, edst, E);

    // ---- agg1 = mean of x over in-neighbors ----
    {
        int blocks = (NN * 32 + 255) / 256;
        gather_mean<0><<<blocks, 256>>>(x, 128, nullptr, nullptr, agg1);
    }

    const dim3 grid((NN + 127) / 128, 2);

    // ---- h = relu([agg1 | x] @ [W1_l | W1_r]^T + b1) ----
    sage_gemm<1><<<grid, 256, GEMM_DSMEM>>>(agg1, x, W1_l, W1_r, b1_l, hbuf, NN);

    // ---- [y | part] = h @ [W2_l ; W2_r]^T ----
    sage_gemm<2><<<grid, 256, GEMM_DSMEM>>>(hbuf, nullptr, W2_l, W2_r, nullptr, c2, NN);

    // ---- out = mean(y rows) + part + b2 ----
    {
        int blocks = (NN * 32 + 255) / 256;
        gather_mean<1><<<blocks, 256>>>(c2, 256, c2, b2_l, out);
    }
}

// round 10
// speedup vs baseline: 1.0452x; 1.0452x over previous
#include <cuda_runtime.h>
#include <cuda_bf16.h>
#include <cstdint>

constexpr int NN   = 50000;
constexpr int EMAX = 640000;

__device__ int   g_cnt[NN];
__device__ int   g_fill[NN];
__device__ int   g_rowptr[NN + 1];
__device__ int   g_col[EMAX];
__device__ float g_agg1[(size_t)NN * 128];   // mean of x (f32)
__device__ float g_h[(size_t)NN * 256];      // layer-1 output (f32)
__device__ float g_c2[(size_t)NN * 256];     // [y | part] (f32)

// ---------------------------------------------------------------------------
// CSR build
// ---------------------------------------------------------------------------
__global__ void zero_cnt() {
    int i = blockIdx.x * blockDim.x + threadIdx.x;
    if (i < NN) g_cnt[i] = 0;
}

__global__ void hist_kernel(const int* __restrict__ dst, int E) {
    int i = blockIdx.x * blockDim.x + threadIdx.x;
    int stride = gridDim.x * blockDim.x;
    for (; i < E; i += stride)
        atomicAdd(&g_cnt[dst[i]], 1);
}

// single-block scan; also seeds g_fill with the row starts
__global__ void __launch_bounds__(1024, 1) scan_kernel() {
    __shared__ int sums[1024];
    const int tid = threadIdx.x;
    const int CH = (NN + 1023) / 1024;
    const int base = tid * CH;

    int local = 0;
    for (int i = 0; i < CH; i++) {
        int idx = base + i;
        if (idx < NN) local += g_cnt[idx];
    }
    sums[tid] = local;
    __syncthreads();
    for (int d = 1; d < 1024; d <<= 1) {
        int v = (tid >= d) ? sums[tid - d] : 0;
        __syncthreads();
        sums[tid] += v;
        __syncthreads();
    }
    int off = sums[tid] - local;
    for (int i = 0; i < CH; i++) {
        int idx = base + i;
        if (idx < NN) {
            g_rowptr[idx] = off;
            g_fill[idx] = off;
            off += g_cnt[idx];
        }
    }
    if (tid == 1023) g_rowptr[NN] = off;
}

__global__ void place_kernel(const int* __restrict__ src,
                             const int* __restrict__ dst, int E) {
    int i = blockIdx.x * blockDim.x + threadIdx.x;
    int stride = gridDim.x * blockDim.x;
    for (; i < E; i += stride) {
        int pos = atomicAdd(&g_fill[dst[i]], 1);
        g_col[pos] = src[i];
    }
}

// ---------------------------------------------------------------------------
// Gather-mean: one warp per node, 1 float4 per lane, 4-deep unroll.
// FIN=0: out[node*128+..] = mean(feat rows)                      (agg1)
// FIN=1: out = mean(feat rows) + c2[node*256+128+..] + b2        (final)
// ---------------------------------------------------------------------------
template <int FIN>
__global__ void __launch_bounds__(256)
gather_mean(const float* __restrict__ feat, int fstride,
            const float* __restrict__ c2,
            const float* __restrict__ b2,
            float* __restrict__ out) {
    int node = (blockIdx.x * blockDim.x + threadIdx.x) >> 5;
    if (node >= NN) return;
    int lane = threadIdx.x & 31;
    int beg = __ldg(&g_rowptr[node]);
    int end = __ldg(&g_rowptr[node + 1]);

    float4 a0 = make_float4(0.f, 0.f, 0.f, 0.f);
    float4 a1 = make_float4(0.f, 0.f, 0.f, 0.f);
    float4 a2 = make_float4(0.f, 0.f, 0.f, 0.f);
    float4 a3 = make_float4(0.f, 0.f, 0.f, 0.f);
    int e = beg;
    for (; e + 3 < end; e += 4) {
        int s0 = __ldg(&g_col[e]);
        int s1 = __ldg(&g_col[e + 1]);
        int s2 = __ldg(&g_col[e + 2]);
        int s3 = __ldg(&g_col[e + 3]);
        float4 v0 = __ldg(reinterpret_cast<const float4*>(feat + (size_t)s0 * fstride) + lane);
        float4 v1 = __ldg(reinterpret_cast<const float4*>(feat + (size_t)s1 * fstride) + lane);
        float4 v2 = __ldg(reinterpret_cast<const float4*>(feat + (size_t)s2 * fstride) + lane);
        float4 v3 = __ldg(reinterpret_cast<const float4*>(feat + (size_t)s3 * fstride) + lane);
        a0.x += v0.x; a0.y += v0.y; a0.z += v0.z; a0.w += v0.w;
        a1.x += v1.x; a1.y += v1.y; a1.z += v1.z; a1.w += v1.w;
        a2.x += v2.x; a2.y += v2.y; a2.z += v2.z; a2.w += v2.w;
        a3.x += v3.x; a3.y += v3.y; a3.z += v3.z; a3.w += v3.w;
    }
    for (; e < end; e++) {
        int s0 = __ldg(&g_col[e]);
        float4 v0 = __ldg(reinterpret_cast<const float4*>(feat + (size_t)s0 * fstride) + lane);
        a0.x += v0.x; a0.y += v0.y; a0.z += v0.z; a0.w += v0.w;
    }
    float inv = 1.0f / (float)max(end - beg, 1);
    float4 r;
    r.x = (a0.x + a1.x + a2.x + a3.x) * inv;
    r.y = (a0.y + a1.y + a2.y + a3.y) * inv;
    r.z = (a0.z + a1.z + a2.z + a3.z) * inv;
    r.w = (a0.w + a1.w + a2.w + a3.w) * inv;

    if (FIN) {
        float4 p = *reinterpret_cast<const float4*>(c2 + (size_t)node * 256 + 128 + lane * 4);
        float4 b = __ldg(reinterpret_cast<const float4*>(b2) + lane);
        r.x += p.x + b.x;
        r.y += p.y + b.y;
        r.z += p.z + b.z;
        r.w += p.w + b.w;
    }
    *(reinterpret_cast<float4*>(out + (size_t)node * 128) + lane) = r;
}

// ---------------------------------------------------------------------------
// mma.sync m16n8k16 bf16 + split helpers
// ---------------------------------------------------------------------------
__device__ __forceinline__ void mma_bf16(float* d, const uint32_t* a,
                                         const uint32_t* b) {
    asm volatile(
        "mma.sync.aligned.m16n8k16.row.col.f32.bf16.bf16.f32 "
        "{%0,%1,%2,%3}, {%4,%5,%6,%7}, {%8,%9}, {%0,%1,%2,%3};"
        : "+f"(d[0]), "+f"(d[1]), "+f"(d[2]), "+f"(d[3])
        : "r"(a[0]), "r"(a[1]), "r"(a[2]), "r"(a[3]), "r"(b[0]), "r"(b[1]));
}

__device__ __forceinline__ void split2(float x, float y,
                                       uint32_t& hi, uint32_t& lo) {
    __nv_bfloat162 h = __floats2bfloat162_rn(x, y);
    __nv_bfloat162 l = __floats2bfloat162_rn(x - __bfloat162float(h.x),
                                             y - __bfloat162float(h.y));
    hi = *reinterpret_cast<uint32_t*>(&h);
    lo = *reinterpret_cast<uint32_t*>(&l);
}

// ---------------------------------------------------------------------------
// Split-bf16 HMMA GEMM — R5 structure, BK=64 (4 chunks): load->sync->MMA->sync.
// C[M,256] = act(A[M,256] @ B[256,256]^T (+bias)); 3-term split, fp32 accum.
// MODE 1: A = [agg1 | x] (chunks 0-1 agg1, 2-3 x), B = [W1_l|W1_r], relu+bias.
// MODE 2: A = h (ld 256), B rows: n<128 -> W2_l else W2_r.
// ---------------------------------------------------------------------------
constexpr int PAD = 72;                         // 64 data + 8 pad (conflict-free)
constexpr int PLANE = 128 * PAD;                // bf16 elems per plane
constexpr int GEMM_DSMEM = 4 * PLANE * 2;       // 73728 B

template <int MODE>
__global__ void __launch_bounds__(256, 2)
sage_gemm(const float* __restrict__ A0, const float* __restrict__ A1,
          const float* __restrict__ B0, const float* __restrict__ B1,
          const float* __restrict__ bias,
          float* __restrict__ C, int M) {
    extern __shared__ char dynsmem[];
    __nv_bfloat16* AH = reinterpret_cast<__nv_bfloat16*>(dynsmem);
    __nv_bfloat16* AL = AH + PLANE;
    __nv_bfloat16* BH = AL + PLANE;
    __nv_bfloat16* BL = BH + PLANE;

    const int tid = threadIdx.x;
    const int wid = tid >> 5, lane = tid & 31;
    const int wm = wid & 3, wn = wid >> 2;
    const int m0 = blockIdx.x * 128, n0 = blockIdx.y * 128;

    float acc[2][8][4];
#pragma unroll
    for (int i = 0; i < 2; i++)
#pragma unroll
        for (int j = 0; j < 8; j++)
#pragma unroll
            for (int q = 0; q < 4; q++) acc[i][j][q] = 0.f;

    for (int ch = 0; ch < 4; ch++) {
        // ---- A tile: 128 rows x 64 f32 = 2048 float4; 8 per thread ----
        const float* Ap;
        int ldA, ka;
        if (MODE == 1) {
            if (ch < 2) { Ap = A0; ka = ch * 64; }
            else        { Ap = A1; ka = (ch - 2) * 64; }
            ldA = 128;
        } else {
            Ap = A0; ldA = 256; ka = ch * 64;
        }
#pragma unroll
        for (int it = 0; it < 8; it++) {
            int idx = it * 256 + tid;
            int row = idx >> 4, f = idx & 15;      // 16 float4 per 64-f row
            int gm = m0 + row;
            float4 v = make_float4(0.f, 0.f, 0.f, 0.f);
            if (gm < M)
                v = __ldg(reinterpret_cast<const float4*>(Ap + (size_t)gm * ldA + ka + f * 4));
            uint32_t h01, l01, h23, l23;
            split2(v.x, v.y, h01, l01);
            split2(v.z, v.w, h23, l23);
            int off = row * PAD + f * 4;
            *reinterpret_cast<uint2*>(&AH[off]) = make_uint2(h01, h23);
            *reinterpret_cast<uint2*>(&AL[off]) = make_uint2(l01, l23);
        }
        // ---- B tile: 128 n-rows x 64 f32 ----
#pragma unroll
        for (int it = 0; it < 8; it++) {
            int idx = it * 256 + tid;
            int row = idx >> 4, f = idx & 15;
            int n = n0 + row;
            const float* bp;
            if (MODE == 1)
                bp = ((ch < 2) ? B0 : B1) + (size_t)n * 128 + ka;
            else
                bp = ((n < 128) ? (B0 + (size_t)n * 256)
                                : (B1 + (size_t)(n - 128) * 256)) + ka;
            float4 v = __ldg(reinterpret_cast<const float4*>(bp + f * 4));
            uint32_t h01, l01, h23, l23;
            split2(v.x, v.y, h01, l01);
            split2(v.z, v.w, h23, l23);
            int off = row * PAD + f * 4;
            *reinterpret_cast<uint2*>(&BH[off]) = make_uint2(h01, h23);
            *reinterpret_cast<uint2*>(&BL[off]) = make_uint2(l01, l23);
        }
        __syncthreads();

        // ---- MMA: 4 k16 sub-steps ----
        const int r = lane >> 2, c = (lane & 3) * 2;
#pragma unroll
        for (int ks = 0; ks < 4; ks++) {
            const int k = ks * 16;
            uint32_t ahi[2][4], alo[2][4];
#pragma unroll
            for (int mt = 0; mt < 2; mt++) {
                int rr = wm * 32 + mt * 16 + r;
                ahi[mt][0] = *reinterpret_cast<const uint32_t*>(&AH[rr * PAD + k + c]);
                ahi[mt][1] = *reinterpret_cast<const uint32_t*>(&AH[(rr + 8) * PAD + k + c]);
                ahi[mt][2] = *reinterpret_cast<const uint32_t*>(&AH[rr * PAD + k + c + 8]);
                ahi[mt][3] = *reinterpret_cast<const uint32_t*>(&AH[(rr + 8) * PAD + k + c + 8]);
                alo[mt][0] = *reinterpret_cast<const uint32_t*>(&AL[rr * PAD + k + c]);
                alo[mt][1] = *reinterpret_cast<const uint32_t*>(&AL[(rr + 8) * PAD + k + c]);
                alo[mt][2] = *reinterpret_cast<const uint32_t*>(&AL[rr * PAD + k + c + 8]);
                alo[mt][3] = *reinterpret_cast<const uint32_t*>(&AL[(rr + 8) * PAD + k + c + 8]);
            }
#pragma unroll
            for (int nt = 0; nt < 8; nt++) {
                int nn = wn * 64 + nt * 8 + (lane >> 2);
                int kb = k + (lane & 3) * 2;
                uint32_t bhi[2], blo[2];
                bhi[0] = *reinterpret_cast<const uint32_t*>(&BH[nn * PAD + kb]);
                bhi[1] = *reinterpret_cast<const uint32_t*>(&BH[nn * PAD + kb + 8]);
                blo[0] = *reinterpret_cast<const uint32_t*>(&BL[nn * PAD + kb]);
                blo[1] = *reinterpret_cast<const uint32_t*>(&BL[nn * PAD + kb + 8]);
#pragma unroll
                for (int mt = 0; mt < 2; mt++) {
                    mma_bf16(acc[mt][nt], ahi[mt], bhi);
                    mma_bf16(acc[mt][nt], ahi[mt], blo);
                    mma_bf16(acc[mt][nt], alo[mt], bhi);
                }
            }
        }
        __syncthreads();
    }

    // ---- epilogue (f32 out) ----
#pragma unroll
    for (int mt = 0; mt < 2; mt++) {
#pragma unroll
        for (int nt = 0; nt < 8; nt++) {
            int m = m0 + wm * 32 + mt * 16 + (lane >> 2);
            int n = n0 + wn * 64 + nt * 8 + (lane & 3) * 2;
            float2 bz = make_float2(0.f, 0.f);
            if (MODE == 1)
                bz = *reinterpret_cast<const float2*>(bias + n);
            if (m < M) {
                float2 v;
                v.x = acc[mt][nt][0] + bz.x;
                v.y = acc[mt][nt][1] + bz.y;
                if (MODE == 1) { v.x = fmaxf(v.x, 0.f); v.y = fmaxf(v.y, 0.f); }
                *reinterpret_cast<float2*>(C + (size_t)m * 256 + n) = v;
            }
            if (m + 8 < M) {
                float2 v;
                v.x = acc[mt][nt][2] + bz.x;
                v.y = acc[mt][nt][3] + bz.y;
                if (MODE == 1) { v.x = fmaxf(v.x, 0.f); v.y = fmaxf(v.y, 0.f); }
                *reinterpret_cast<float2*>(C + (size_t)(m + 8) * 256 + n) = v;
            }
        }
    }
}

// ---------------------------------------------------------------------------
// Launch
// ---------------------------------------------------------------------------
extern "C" void kernel_launch(void* const* d_in, const int* in_sizes, int n_in,
                              void* d_out, int out_size) {
    const float* x    = (const float*)d_in[0];
    const int*   ei   = (const int*)d_in[1];
    const float* W1_l = (const float*)d_in[2];
    const float* b1_l = (const float*)d_in[3];
    const float* W1_r = (const float*)d_in[4];
    const float* W2_l = (const float*)d_in[5];
    const float* b2_l = (const float*)d_in[6];
    const float* W2_r = (const float*)d_in[7];
    float* out = (float*)d_out;

    const int E = in_sizes[1] / 2;
    const int* esrc = ei;
    const int* edst = ei + E;

    void *p_agg1, *p_h, *p_c2;
    cudaGetSymbolAddress(&p_agg1, g_agg1);
    cudaGetSymbolAddress(&p_h,    g_h);
    cudaGetSymbolAddress(&p_c2,   g_c2);
    float* agg1 = (float*)p_agg1;
    float* hbuf = (float*)p_h;
    float* c2   = (float*)p_c2;

    cudaFuncSetAttribute(sage_gemm<1>,
                         cudaFuncAttributeMaxDynamicSharedMemorySize, GEMM_DSMEM);
    cudaFuncSetAttribute(sage_gemm<2>,
                         cudaFuncAttributeMaxDynamicSharedMemorySize, GEMM_DSMEM);

    // ---- CSR build (by dst) ----
    zero_cnt<<<(NN + 255) / 256, 256>>>();
    hist_kernel<<<(E + 511) / 512, 256>>>(edst, E);
    scan_kernel<<<1, 1024>>>();
    place_kernel<<<(E + 511) / 512, 256>>>(esrc, edst, E);

    // ---- agg1 = mean of x over in-neighbors ----
    {
        int blocks = (NN * 32 + 255) / 256;
        gather_mean<0><<<blocks, 256>>>(x, 128, nullptr, nullptr, agg1);
    }

    const dim3 grid((NN + 127) / 128, 2);

    // ---- h = relu([agg1 | x] @ [W1_l | W1_r]^T + b1) ----
    sage_gemm<1><<<grid, 256, GEMM_DSMEM>>>(agg1, x, W1_l, W1_r, b1_l, hbuf, NN);

    // ---- [y | part] = h @ [W2_l ; W2_r]^T ----
    sage_gemm<2><<<grid, 256, GEMM_DSMEM>>>(hbuf, nullptr, W2_l, W2_r, nullptr, c2, NN);

    // ---- out = mean(y rows) + part + b2 ----
    {
        int blocks = (NN * 32 + 255) / 256;
        gather_mean<1><<<blocks, 256>>>(c2, 256, c2, b2_l, out);
    }
}